// round 17
// baseline (speedup 1.0000x reference)
#include <cuda_runtime.h>
#include <cuda_fp16.h>
#include <cstdint>

#define D_DIM 512
#define QMAX  2048
#define NPAD  100096   // 782 * 128
#define MAXCAND 4740   // >= ceil(N/128)*6

// ---------------- scratch (device globals; no allocation allowed) -----------
__device__ float g_x2[QMAX];
__device__ float g_t2[NPAD];
__device__ __align__(256) int8_t g_xb[(size_t)QMAX * D_DIM];   // s8, scale QS
__device__ __align__(256) int8_t g_tb[(size_t)NPAD * D_DIM];   // s8, scale QS
// per-(query, 64-col tile) top-3 candidates: u64 = (fp16 score bits << 32) | n
__device__ __align__(16) unsigned long long g_cand[(size_t)QMAX * MAXCAND];

#define SCORE_BIAS 2048.0f
#define QS 31.75f               // int8 scale: +-4.0 sigma -> +-127

// ---------------- helpers ----------------------------------------------------
__device__ __forceinline__ uint32_t smem_u32(const void* p) {
    uint32_t a;
    asm("{ .reg .u64 t; cvta.to.shared.u64 t, %1; cvt.u32.u64 %0, t; }" : "=r"(a) : "l"(p));
    return a;
}
__device__ __forceinline__ void cpasync16(uint32_t saddr, const void* g) {
    asm volatile("cp.async.cg.shared.global [%0], [%1], 16;"
                 :: "r"(saddr), "l"(__cvta_generic_to_global(g)) : "memory");
}
#define CP_COMMIT() asm volatile("cp.async.commit_group;" ::: "memory")
#define CP_WAIT0()  asm volatile("cp.async.wait_group 0;" ::: "memory")

__device__ __forceinline__ void ins3u(uint32_t& b0, uint32_t& b1, uint32_t& b2, uint32_t k) {
    uint32_t t = min(b2, k);
    uint32_t u = min(b1, t);
    b2 = max(b1, t);
    b1 = max(b0, u);
    b0 = min(b0, u);
}
__device__ __forceinline__ void ins3u64(unsigned long long& b0, unsigned long long& b1,
                                        unsigned long long& b2, unsigned long long k) {
    unsigned long long t = k  < b2 ? k  : b2;
    unsigned long long u = t  < b1 ? t  : b1;
    b2 = b1 > t ? b1 : t;
    b1 = b0 > u ? b0 : u;
    b0 = b0 < u ? b0 : u;
}
__device__ __forceinline__ void insert8u64(unsigned long long (&bk)[8], unsigned long long k) {
#pragma unroll
    for (int j = 0; j < 8; ++j)
        if (k < bk[j]) { unsigned long long t = bk[j]; bk[j] = k; k = t; }
}

// ---------------- kernel: fused fp32->s8 quantize + row norms ----------------
__global__ void convert_norm(const float* __restrict__ src, int rows_valid,
                             int rows_total, int which)
{
    int gw   = (blockIdx.x * blockDim.x + threadIdx.x) >> 5;
    int lane = threadIdx.x & 31;
    if (gw >= rows_total) return;
    char4* dst = reinterpret_cast<char4*>((which ? g_tb : g_xb) + (size_t)gw * D_DIM);
    if (gw < rows_valid) {
        const float4* r4 = reinterpret_cast<const float4*>(src + (size_t)gw * D_DIM);
        float s = 0.f;
#pragma unroll
        for (int j = 0; j < 4; ++j) {
            float4 v = r4[lane + j * 32];
            s += v.x * v.x + v.y * v.y + v.z * v.z + v.w * v.w;
            char4 o;
            o.x = (char)max(-127, min(127, __float2int_rn(v.x * QS)));
            o.y = (char)max(-127, min(127, __float2int_rn(v.y * QS)));
            o.z = (char)max(-127, min(127, __float2int_rn(v.z * QS)));
            o.w = (char)max(-127, min(127, __float2int_rn(v.w * QS)));
            dst[lane + j * 32] = o;
        }
#pragma unroll
        for (int o = 16; o; o >>= 1) s += __shfl_xor_sync(0xffffffffu, s, o);
        if (lane == 0) { if (which) g_t2[gw] = s; else g_x2[gw] = s; }
    } else {
        char4 z = make_char4(0, 0, 0, 0);
#pragma unroll
        for (int j = 0; j < 4; ++j) dst[lane + j * 32] = z;
        if (lane == 0 && which) g_t2[gw] = 3.0e38f;
    }
}

// ---------------- mma.sync m16n8k32 s8 wrapper (portable, sm_80+) ------------
__device__ __forceinline__ void imma16832(int* c, const uint32_t* a, const uint32_t* b) {
    asm volatile(
        "mma.sync.aligned.m16n8k32.row.col.s32.s8.s8.s32 "
        "{%0,%1,%2,%3}, {%4,%5,%6,%7}, {%8,%9}, {%0,%1,%2,%3};"
        : "+r"(c[0]), "+r"(c[1]), "+r"(c[2]), "+r"(c[3])
        : "r"(a[0]), "r"(a[1]), "r"(a[2]), "r"(a[3]), "r"(b[0]), "r"(b[1]));
}

// ---------------- kernel: s8 IMMA GEMM + fused candidate selection -----------
// chunk = 64 s8 elems = 64 bytes/row: byte layout identical to R16 fp8.
#define BM 128
#define BN 128
#define BKB 64                  // bytes (= s8 elems) per chunk
#define NCHUNK (D_DIM / BKB)    // 8
#define SROW 80
#define ABYTES (BM * SROW)
#define BBYTES (BN * SROW)

__global__ __launch_bounds__(256, 2) void dist_gemm_mma(int N, int Q, int cstride)
{
    __shared__ __align__(16) char smA[2][ABYTES];
    __shared__ __align__(16) char smB[2][BBYTES];

    const int tid = threadIdx.x;
    const int wid = tid >> 5;
    const int lane = tid & 31;
    const int tq = lane >> 2, tr = lane & 3;
    const int wm = wid & 3, wn = wid >> 2;
    const int bq = blockIdx.y * BM, bn = blockIdx.x * BN;

    const int lrow = tid >> 2;
    const int lseg = tid & 3;
    const int kseg = lseg * 16;                // byte offset within chunk
    const int ssm  = lrow * SROW + lseg * 16;
    int ar0 = bq + lrow;        if (ar0 > Q - 1) ar0 = Q - 1;
    int ar1 = bq + lrow + 64;   if (ar1 > Q - 1) ar1 = Q - 1;
    const size_t aoff0 = (size_t)ar0 * D_DIM;  // bytes (1 B/elem)
    const size_t aoff1 = (size_t)ar1 * D_DIM;
    const size_t boff0 = (size_t)(bn + lrow) * D_DIM;
    const size_t boff1 = (size_t)(bn + lrow + 64) * D_DIM;

    const uint32_t sa[2] = { smem_u32(smA[0]) + ssm, smem_u32(smA[1]) + ssm };
    const uint32_t sb[2] = { smem_u32(smB[0]) + ssm, smem_u32(smB[1]) + ssm };

    int c[2][8][4];
#pragma unroll
    for (int mi = 0; mi < 2; ++mi)
#pragma unroll
        for (int ni = 0; ni < 8; ++ni)
#pragma unroll
            for (int j = 0; j < 4; ++j) c[mi][ni][j] = 0;

    cpasync16(sa[0],             g_xb + aoff0 + kseg);
    cpasync16(sa[0] + 64 * SROW, g_xb + aoff1 + kseg);
    cpasync16(sb[0],             g_tb + boff0 + kseg);
    cpasync16(sb[0] + 64 * SROW, g_tb + boff1 + kseg);
    CP_COMMIT();
    CP_WAIT0();
    __syncthreads();

#pragma unroll 2
    for (int kc = 0; kc < NCHUNK; ++kc) {
        const bool pre = (kc + 1) < NCHUNK;
        if (pre) {
            const int ko = (kc + 1) * BKB + kseg;
            const int nb = (kc + 1) & 1;
            cpasync16(sa[nb],             g_xb + aoff0 + ko);
            cpasync16(sa[nb] + 64 * SROW, g_xb + aoff1 + ko);
            cpasync16(sb[nb],             g_tb + boff0 + ko);
            cpasync16(sb[nb] + 64 * SROW, g_tb + boff1 + ko);
            CP_COMMIT();
        }
        const char* sA = smA[kc & 1];
        const char* sB = smB[kc & 1];
#pragma unroll
        for (int ks = 0; ks < 2; ++ks) {       // ks covers 32 s8 = 32 bytes
            uint32_t a[2][4], b[8][2];
#pragma unroll
            for (int mi = 0; mi < 2; ++mi) {
                const char* p = sA + (wm * 32 + mi * 16 + tq) * SROW + ks * 32 + tr * 4;
                a[mi][0] = *reinterpret_cast<const uint32_t*>(p);
                a[mi][1] = *reinterpret_cast<const uint32_t*>(p + 8 * SROW);
                a[mi][2] = *reinterpret_cast<const uint32_t*>(p + 16);
                a[mi][3] = *reinterpret_cast<const uint32_t*>(p + 8 * SROW + 16);
            }
#pragma unroll
            for (int ni = 0; ni < 8; ++ni) {
                const char* p = sB + (wn * 64 + ni * 8 + tq) * SROW + ks * 32 + tr * 4;
                b[ni][0] = *reinterpret_cast<const uint32_t*>(p);
                b[ni][1] = *reinterpret_cast<const uint32_t*>(p + 16);
            }
#pragma unroll
            for (int mi = 0; mi < 2; ++mi)
#pragma unroll
                for (int ni = 0; ni < 8; ++ni)
                    imma16832(c[mi][ni], a[mi], b[ni]);
        }
        if (pre) {
            CP_WAIT0();
            __syncthreads();
        }
    }

    // ---- fused epilogue: per-(query, 64-col warp tile) top-3 candidates ----
    const float DESCALE = 2.0f / (QS * QS);
    float t2v[16];
#pragma unroll
    for (int ni = 0; ni < 8; ++ni) {
        t2v[ni * 2 + 0] = g_t2[bn + wn * 64 + ni * 8 + tr * 2 + 0] + SCORE_BIAS;
        t2v[ni * 2 + 1] = g_t2[bn + wn * 64 + ni * 8 + tr * 2 + 1] + SCORE_BIAS;
    }

#pragma unroll
    for (int mi = 0; mi < 2; ++mi) {
#pragma unroll
        for (int h = 0; h < 2; ++h) {
            const int q = bq + wm * 32 + mi * 16 + tq + h * 8;
            uint32_t k0 = 0xFFFFFFFFu, k1 = 0xFFFFFFFFu;
#pragma unroll
            for (int ni = 0; ni < 8; ++ni) {
#pragma unroll
                for (int sub = 0; sub < 2; ++sub) {
                    float s = t2v[ni * 2 + sub]
                            - DESCALE * (float)c[mi][ni][h * 2 + sub];
                    uint32_t hb = (uint32_t)__half_as_ushort(__float2half_rn(s));
                    uint32_t key = (hb << 16) | (uint32_t)(ni * 8 + tr * 2 + sub);
                    uint32_t t = min(k1, key);
                    k1 = max(k0, t);
                    k0 = min(k0, t);
                }
            }
            uint32_t b0 = k0, b1 = k1, b2 = 0xFFFFFFFFu;
            {
                uint32_t r0 = __shfl_xor_sync(0xffffffffu, b0, 1);
                uint32_t r1 = __shfl_xor_sync(0xffffffffu, b1, 1);
                ins3u(b0, b1, b2, r0);
                ins3u(b0, b1, b2, r1);
            }
            {
                uint32_t r0 = __shfl_xor_sync(0xffffffffu, b0, 2);
                uint32_t r1 = __shfl_xor_sync(0xffffffffu, b1, 2);
                uint32_t r2 = __shfl_xor_sync(0xffffffffu, b2, 2);
                ins3u(b0, b1, b2, r0);
                ins3u(b0, b1, b2, r1);
                ins3u(b0, b1, b2, r2);
            }
            if (tr == 0 && q < Q) {
                const int ncol = bn + wn * 64;
                unsigned long long* dst =
                    g_cand + (size_t)q * cstride + ((size_t)blockIdx.x * 2 + wn) * 3;
                dst[0] = ((unsigned long long)(b0 >> 16) << 32) | (uint32_t)(ncol + (b0 & 63u));
                dst[1] = ((unsigned long long)(b1 >> 16) << 32) | (uint32_t)(ncol + (b1 & 63u));
                dst[2] = ((unsigned long long)(b2 >> 16) << 32) | (uint32_t)(ncol + (b2 & 63u));
            }
        }
    }
}

// ---------------- final: merge candidates -> top-64 -> exact rerank ----------
#define TKT 256

__global__ __launch_bounds__(TKT) void topk_rerank(
    const float* __restrict__ X, const float* __restrict__ T,
    const int* __restrict__ labels, float* __restrict__ out,
    int N, int Q, int out_size, int ncand)
{
    const int q = blockIdx.x;
    const int tid = threadIdx.x;
    const int lane = tid & 31, wid = tid >> 5;
    const unsigned long long* crow = g_cand + (size_t)q * ncand;

    unsigned long long b0 = ~0ull, b1 = ~0ull, b2 = ~0ull;
    for (int i = tid; i < ncand; i += TKT)
        ins3u64(b0, b1, b2, crow[i]);

    __shared__ unsigned long long sk[TKT * 3];
    sk[tid * 3 + 0] = b0;
    sk[tid * 3 + 1] = b1;
    sk[tid * 3 + 2] = b2;
    __syncthreads();

    __shared__ int wiv[64];
    if (lane == 0) {
        unsigned long long mk[8];
#pragma unroll
        for (int t = 0; t < 8; ++t) mk[t] = ~0ull;
        unsigned long long mthr = ~0ull;
        const int base = wid * 96;
        for (int t = 0; t < 96; ++t) {
            unsigned long long k = sk[base + t];
            if (k < mthr) { insert8u64(mk, k); mthr = mk[7]; }
        }
#pragma unroll
        for (int t = 0; t < 8; ++t)
            wiv[wid * 8 + t] = (int)(uint32_t)(mk[t] & 0xFFFFFFFFull);
    }
    __syncthreads();

    __shared__ float ed[64];
    {
        const float4* x4 = reinterpret_cast<const float4*>(X + (size_t)q * D_DIM);
        float4 xv[4];
#pragma unroll
        for (int jj = 0; jj < 4; ++jj) xv[jj] = x4[lane + jj * 32];
        for (int cc = 0; cc < 8; ++cc) {
            int idx = wiv[wid * 8 + cc];
            float d2 = 3.4e38f;
            if (idx >= 0 && idx < N) {
                const float4* t4 = reinterpret_cast<const float4*>(T + (size_t)idx * D_DIM);
                float dot = 0.f;
#pragma unroll
                for (int jj = 0; jj < 4; ++jj) {
                    float4 tv = t4[lane + jj * 32];
                    dot += xv[jj].x * tv.x + xv[jj].y * tv.y + xv[jj].z * tv.z + xv[jj].w * tv.w;
                }
#pragma unroll
                for (int o = 16; o; o >>= 1) dot += __shfl_xor_sync(0xffffffffu, dot, o);
                d2 = g_x2[q] + g_t2[idx] - 2.f * dot;
            }
            if (lane == 0) ed[wid * 8 + cc] = d2;
        }
    }
    __syncthreads();

    if (tid == 0) {
        float fd[5]; int fi[5];
#pragma unroll
        for (int t = 0; t < 5; ++t) { fd[t] = 3.4e38f; fi[t] = 0x7fffffff; }
        for (int t = 0; t < 64; ++t) {
            float vd = ed[t]; int vi = wiv[t];
#pragma unroll
            for (int jj = 0; jj < 5; ++jj) {
                bool lt = (vd < fd[jj]) || (vd == fd[jj] && vi < fi[jj]);
                if (lt) { float td = fd[jj]; int ti = fi[jj];
                          fd[jj] = vd; fi[jj] = vi; vd = td; vi = ti; }
            }
        }
        const int Q5 = Q * 5;
#pragma unroll
        for (int jj = 0; jj < 5; ++jj) {
            float dist = sqrtf(fmaxf(fd[jj], 0.f));
            int idx = fi[jj];
            int o0 = q * 5 + jj;
            int o1 = Q5 + q * 5 + jj;
            int o2 = 2 * Q5 + jj * Q + q;
            if (o0 < out_size) out[o0] = dist;
            if (o1 < out_size) out[o1] = (float)idx;
            if (o2 < out_size) out[o2] = (float)labels[idx];
        }
    }
}

// ---------------- launch -----------------------------------------------------
extern "C" void kernel_launch(void* const* d_in, const int* in_sizes, int n_in,
                              void* d_out, int out_size)
{
    const float* X      = (const float*)d_in[0];
    const float* T      = (const float*)d_in[1];
    const int*   labels = (const int*)d_in[2];
    const int Q = in_sizes[0] / D_DIM;
    const int N = in_sizes[2];

    convert_norm<<<(Q * 32 + 255) / 256, 256>>>(X, Q, Q, 0);
    convert_norm<<<(NPAD * 32 + 255) / 256, 256>>>(T, N, NPAD, 1);

    const int ntiles = (N + BN - 1) / BN;
    const int cstride = ntiles * 6;

    dim3 grid(ntiles, (Q + BM - 1) / BM);
    dist_gemm_mma<<<grid, 256>>>(N, Q, cstride);

    topk_rerank<<<Q, TKT>>>(X, T, labels, (float*)d_out, N, Q, out_size, cstride);
}